// round 10
// baseline (speedup 1.0000x reference)
#include <cuda_runtime.h>

typedef unsigned long long ull;

#define TT   512
#define BB   256
#define DIN  85
#define HH   512
#define NOUT 33

constexpr size_t GSc = (size_t)TT * HH * BB;   // elements per gate

// Scratch (allocation-free rule: __device__ globals)
__device__ float g_pre[4 * GSc];   // [gate][t][h][b]
__device__ float g_hid[GSc];       // [t][h][b]
__device__ unsigned g_flags[TT * 2 * 64];   // [t][grp][hblk] completion flags

// ---------- packed fp32x2 helpers ----------
__device__ __forceinline__ ull pack2(float x, float y) {
    ull v;
    asm("mov.b64 %0, {%1, %2};" : "=l"(v)
        : "r"(__float_as_uint(x)), "r"(__float_as_uint(y)));
    return v;
}
__device__ __forceinline__ float2 unpack2(ull v) {
    unsigned a, b;
    asm("mov.b64 {%0, %1}, %2;" : "=r"(a), "=r"(b) : "l"(v));
    return make_float2(__uint_as_float(a), __uint_as_float(b));
}
#define FMA2(acc, a, b) \
    asm("fma.rn.f32x2 %0, %1, %2, %0;" : "+l"(acc) : "l"(a), "l"(b))

// ---------- fast activations (validated rel err ~4e-7 final) ----------
__device__ __forceinline__ float sigf(float x) {
    x = fminf(fmaxf(x, -30.f), 30.f);
    return __fdividef(1.f, 1.f + __expf(-x));
}
__device__ __forceinline__ float tanh_fast(float x) {
    x = fminf(fmaxf(x, -15.f), 15.f);
    float e = __expf(-2.f * x);
    return __fdividef(1.f - e, 1.f + e);
}

// ---------- cp.async helpers ----------
__device__ __forceinline__ unsigned smem_u32(const void* p) {
    return (unsigned)__cvta_generic_to_shared(p);
}
__device__ __forceinline__ void cp16(unsigned dst, const void* src) {
    asm volatile("cp.async.cg.shared.global [%0], [%1], 16;" :: "r"(dst), "l"(src));
}
#define CP_COMMIT() asm volatile("cp.async.commit_group;")
template<int N> __device__ __forceinline__ void cp_wait() {
    asm volatile("cp.async.wait_group %0;" :: "n"(N));
}

// =====================================================================
// Phase 1: input projections  pre[g][t][h][b] = sum_i x[t,b,i] * Wxg[h,i]
// One CTA per t; warp processes 4 gate-rows at a time (x loads amortized).
// =====================================================================
__global__ void __launch_bounds__(256, 1) k_input_proj(
    const float* __restrict__ x,
    const float* __restrict__ Wxi, const float* __restrict__ Wxf,
    const float* __restrict__ Wxo, const float* __restrict__ Wxc)
{
    extern __shared__ float xs[];          // [85][258]
    const int t = blockIdx.x;
    const float* xt = x + (size_t)t * BB * DIN;
    for (int idx = threadIdx.x; idx < BB * DIN; idx += 256) {
        int b = idx / DIN;
        int i = idx - b * DIN;
        xs[i * 258 + b] = xt[idx];
    }
    __syncthreads();

    const int warp = threadIdx.x >> 5;
    const int lane = threadIdx.x & 31;

    for (int r4 = warp * 4; r4 < 4 * HH; r4 += 32) {
        const int g = r4 >> 9;
        const int h = r4 & (HH - 1);
        const float* wrow;
        if      (g == 0) wrow = Wxi + h * DIN;
        else if (g == 1) wrow = Wxf + h * DIN;
        else if (g == 2) wrow = Wxo + h * DIN;
        else             wrow = Wxc + h * DIN;

        ull acc[4][4];
#pragma unroll
        for (int rr = 0; rr < 4; rr++)
#pragma unroll
            for (int q = 0; q < 4; q++) acc[rr][q] = 0;

#pragma unroll 5
        for (int i = 0; i < DIN; i++) {
            const ull* xr = (const ull*)(xs + i * 258);
            ull x0 = xr[lane], x1 = xr[lane + 32];
            ull x2 = xr[lane + 64], x3 = xr[lane + 96];
#pragma unroll
            for (int rr = 0; rr < 4; rr++) {
                float w = __ldg(wrow + rr * DIN + i);
                ull w2 = pack2(w, w);
                FMA2(acc[rr][0], w2, x0);
                FMA2(acc[rr][1], w2, x1);
                FMA2(acc[rr][2], w2, x2);
                FMA2(acc[rr][3], w2, x3);
            }
        }
#pragma unroll
        for (int rr = 0; rr < 4; rr++) {
            ull* pp = (ull*)(g_pre + (size_t)g * GSc +
                             ((size_t)t * HH + h + rr) * BB);
            pp[lane]      = acc[rr][0];
            pp[lane + 32] = acc[rr][1];
            pp[lane + 64] = acc[rr][2];
            pp[lane + 96] = acc[rr][3];
        }
    }
}

// =====================================================================
// Phase 2: persistent recurrence, dataflow-synchronized.
// 128 CTAs x 128 threads. CTA tile: 8 h (32 gate rows) x 128 b.
//   grp  = blockIdx.x & 1   -> b0 = grp*128   (b-groups are independent)
//   hblk = blockIdx.x >> 1  -> h0 = hblk*8
// Thread: hm = tid & 7 (one h, all 4 gates), bq = tid >> 3 (8 b values).
// SMEM: sW[512 k][64] = per k, 8h x {wI,wI,wF,wF,wO,wO,wC,wC} (128 KB)
//       sH double buffer 2 x [64 k][128 b] (64 KB) via cp.async.
// Sync: per-(t,hblk) flags; consumer polls the 8 producer flags of each
//       64-row chunk just before staging it. No global barrier.
// =====================================================================
__global__ void __launch_bounds__(128, 1) k_lstm_rec(
    const float* __restrict__ Whi, const float* __restrict__ Whf,
    const float* __restrict__ Who, const float* __restrict__ Whc,
    const float* __restrict__ bhi, const float* __restrict__ bhf,
    const float* __restrict__ bho, const float* __restrict__ bhc)
{
    extern __shared__ float smem_f[];
    float* sW = smem_f;                    // 32768 floats (128 KB)
    float* sH = smem_f + 32768;            // 2 x 8192 floats (64 KB)
    const unsigned sH_u32 = smem_u32(sH);

    const int tid  = threadIdx.x;
    const int hm   = tid & 7;
    const int bq   = tid >> 3;             // 0..15
    const int grp  = blockIdx.x & 1;
    const int hblk = blockIdx.x >> 1;      // 0..63
    const int h0   = hblk * 8;
    const int h    = h0 + hm;
    const int b0   = grp * 128;
    const int bb   = b0 + bq * 8;          // this thread's 8 b values

    // One-time duplicated W load: sW[k*64 + hm*8 + 2g + d] = W_g[h0+hm][k]
    for (int idx = tid; idx < 512 * 64; idx += 128) {
        int k  = idx >> 6;
        int r  = idx & 63;
        int hl = r >> 3;
        int g  = (r >> 1) & 3;
        int src = (h0 + hl) * HH + k;
        float w;
        if      (g == 0) w = Whi[src];
        else if (g == 1) w = Whf[src];
        else if (g == 2) w = Who[src];
        else             w = Whc[src];
        sW[idx] = w;
    }
    const float bi  = bhi[h], bf_ = bhf[h], bo = bho[h], bc = bhc[h];
    float C[8];
#pragma unroll
    for (int j = 0; j < 8; j++) C[j] = 0.f;
    __syncthreads();

    // per-thread SMEM pointers
    const ulonglong2* wpt = (const ulonglong2*)sW + hm * 2;  // [k*16], [k*16+1]

#pragma unroll 1
    for (int t = 0; t < TT; t++) {
        // Prefetch gate pre-activations (hidden under the GEMM)
        const float* pb = g_pre + ((size_t)t * HH + h) * BB + bb;
        float4 xi0 = *(const float4*)(pb);
        float4 xi1 = *(const float4*)(pb + 4);
        float4 xf0 = *(const float4*)(pb + GSc);
        float4 xf1 = *(const float4*)(pb + GSc + 4);
        float4 xo0 = *(const float4*)(pb + 2 * GSc);
        float4 xo1 = *(const float4*)(pb + 2 * GSc + 4);
        float4 xc0 = *(const float4*)(pb + 3 * GSc);
        float4 xc1 = *(const float4*)(pb + 3 * GSc + 4);

        ull aI[4], aF[4], aO[4], aC[4];
#pragma unroll
        for (int j = 0; j < 4; j++) { aI[j] = 0; aF[j] = 0; aO[j] = 0; aC[j] = 0; }

        if (t > 0) {
            const float* hsrc = g_hid + (size_t)(t - 1) * HH * BB + b0;
            const unsigned fbase = (unsigned)((t - 1) * 2 + grp) * 64;

            // ---- wait for chunk 0 producers, stage chunk 0 ----
            if (tid < 8) {
                volatile unsigned* f = g_flags + fbase + tid;
                while (*f == 0u) __nanosleep(20);
                __threadfence();
            }
            __syncthreads();
            {
#pragma unroll
                for (int j = 0; j < 16; j++) {
                    int i = tid + j * 128;         // 0..2047
                    int row = i >> 5, col = i & 31;
                    cp16(sH_u32 + (unsigned)i * 16, hsrc + row * BB + col * 4);
                }
                CP_COMMIT();
            }
            // pre-poll chunk 1
            if (tid < 8) {
                volatile unsigned* f = g_flags + fbase + 8 + tid;
                while (*f == 0u) __nanosleep(20);
                __threadfence();
            }
            __syncthreads();

#pragma unroll 1
            for (int c = 0; c < 8; c++) {
                if (c < 7) {   // stage chunk c+1 (flags already confirmed)
                    const float* src = hsrc + (size_t)(c + 1) * 64 * BB;
                    unsigned dstb = sH_u32 + (unsigned)(((c + 1) & 1) ? 32768 : 0);
#pragma unroll
                    for (int j = 0; j < 16; j++) {
                        int i = tid + j * 128;
                        int row = i >> 5, col = i & 31;
                        cp16(dstb + (unsigned)i * 16, src + row * BB + col * 4);
                    }
                    CP_COMMIT();
                    cp_wait<1>();
                } else {
                    cp_wait<0>();
                }
                __syncthreads();

                const ulonglong2* hpt =
                    (const ulonglong2*)(sH + (c & 1) * 8192) + bq * 2;
                const int kb = c * 64;

#pragma unroll 4
                for (int kl = 0; kl < 64; kl++) {
                    ulonglong2 wIF = wpt[(kb + kl) * 16];       // {I,I},{F,F}
                    ulonglong2 wOC = wpt[(kb + kl) * 16 + 1];   // {O,O},{C,C}
                    ulonglong2 h01 = hpt[kl * 32];              // b0..b3
                    ulonglong2 h23 = hpt[kl * 32 + 1];          // b4..b7
                    FMA2(aI[0], wIF.x, h01.x); FMA2(aI[1], wIF.x, h01.y);
                    FMA2(aI[2], wIF.x, h23.x); FMA2(aI[3], wIF.x, h23.y);
                    FMA2(aF[0], wIF.y, h01.x); FMA2(aF[1], wIF.y, h01.y);
                    FMA2(aF[2], wIF.y, h23.x); FMA2(aF[3], wIF.y, h23.y);
                    FMA2(aO[0], wOC.x, h01.x); FMA2(aO[1], wOC.x, h01.y);
                    FMA2(aO[2], wOC.x, h23.x); FMA2(aO[3], wOC.x, h23.y);
                    FMA2(aC[0], wOC.y, h01.x); FMA2(aC[1], wOC.y, h01.y);
                    FMA2(aC[2], wOC.y, h23.x); FMA2(aC[3], wOC.y, h23.y);
                }

                // pre-poll chunk c+2 while others finish compute
                if (c < 6 && tid < 8) {
                    volatile unsigned* f = g_flags + fbase + (c + 2) * 8 + tid;
                    while (*f == 0u) __nanosleep(20);
                    __threadfence();
                }
                __syncthreads();
            }
        }

        // ---- epilogue: gates -> cell update -> hidden state (8 b) ----
        float hv[8];
        {
            float2 vI = unpack2(aI[0]), vF = unpack2(aF[0]);
            float2 vO = unpack2(aO[0]), vG = unpack2(aC[0]);
            float I = sigf(vI.x + xi0.x + bi), F = sigf(vF.x + xf0.x + bf_);
            float O = sigf(vO.x + xo0.x + bo), G = tanh_fast(vG.x + xc0.x + bc);
            C[0] = F * C[0] + I * G;  hv[0] = O * tanh_fast(C[0]);
            I = sigf(vI.y + xi0.y + bi);  F = sigf(vF.y + xf0.y + bf_);
            O = sigf(vO.y + xo0.y + bo);  G = tanh_fast(vG.y + xc0.y + bc);
            C[1] = F * C[1] + I * G;  hv[1] = O * tanh_fast(C[1]);
        }
        {
            float2 vI = unpack2(aI[1]), vF = unpack2(aF[1]);
            float2 vO = unpack2(aO[1]), vG = unpack2(aC[1]);
            float I = sigf(vI.x + xi0.z + bi), F = sigf(vF.x + xf0.z + bf_);
            float O = sigf(vO.x + xo0.z + bo), G = tanh_fast(vG.x + xc0.z + bc);
            C[2] = F * C[2] + I * G;  hv[2] = O * tanh_fast(C[2]);
            I = sigf(vI.y + xi0.w + bi);  F = sigf(vF.y + xf0.w + bf_);
            O = sigf(vO.y + xo0.w + bo);  G = tanh_fast(vG.y + xc0.w + bc);
            C[3] = F * C[3] + I * G;  hv[3] = O * tanh_fast(C[3]);
        }
        {
            float2 vI = unpack2(aI[2]), vF = unpack2(aF[2]);
            float2 vO = unpack2(aO[2]), vG = unpack2(aC[2]);
            float I = sigf(vI.x + xi1.x + bi), F = sigf(vF.x + xf1.x + bf_);
            float O = sigf(vO.x + xo1.x + bo), G = tanh_fast(vG.x + xc1.x + bc);
            C[4] = F * C[4] + I * G;  hv[4] = O * tanh_fast(C[4]);
            I = sigf(vI.y + xi1.y + bi);  F = sigf(vF.y + xf1.y + bf_);
            O = sigf(vO.y + xo1.y + bo);  G = tanh_fast(vG.y + xc1.y + bc);
            C[5] = F * C[5] + I * G;  hv[5] = O * tanh_fast(C[5]);
        }
        {
            float2 vI = unpack2(aI[3]), vF = unpack2(aF[3]);
            float2 vO = unpack2(aO[3]), vG = unpack2(aC[3]);
            float I = sigf(vI.x + xi1.z + bi), F = sigf(vF.x + xf1.z + bf_);
            float O = sigf(vO.x + xo1.z + bo), G = tanh_fast(vG.x + xc1.z + bc);
            C[6] = F * C[6] + I * G;  hv[6] = O * tanh_fast(C[6]);
            I = sigf(vI.y + xi1.w + bi);  F = sigf(vF.y + xf1.w + bf_);
            O = sigf(vO.y + xo1.w + bo);  G = tanh_fast(vG.y + xc1.w + bc);
            C[7] = F * C[7] + I * G;  hv[7] = O * tanh_fast(C[7]);
        }

        float* op = g_hid + ((size_t)t * HH + h) * BB + bb;
        *(float4*)(op)     = make_float4(hv[0], hv[1], hv[2], hv[3]);
        *(float4*)(op + 4) = make_float4(hv[4], hv[5], hv[6], hv[7]);

        // publish: all stores visible, then set this CTA's flag for step t
        __threadfence();
        __syncthreads();
        if (tid == 0)
            atomicExch(&g_flags[(unsigned)(t * 2 + grp) * 64 + hblk], 1u);
    }
}

// =====================================================================
// Phase 3: readout  out[t][b][o] = sum_h hid[t][h][b]*Wro[o][h] + bro[o]
// =====================================================================
__global__ void __launch_bounds__(256, 1) k_readout(
    const float* __restrict__ Wro, const float* __restrict__ bro,
    float* __restrict__ out)
{
    extern __shared__ float ws[];          // [33][512]
    for (int idx = threadIdx.x; idx < NOUT * HH; idx += 256)
        ws[idx] = Wro[idx];
    __syncthreads();

    const int warp = threadIdx.x >> 5;
    const int lane = threadIdx.x & 31;
    const int t = blockIdx.x;
    const int b = warp * 32 + lane;
    const float* hp = g_hid + (size_t)t * HH * BB + b;

    ull acc[NOUT];
#pragma unroll
    for (int o = 0; o < NOUT; o++) acc[o] = 0;

    for (int hh = 0; hh < HH; hh += 2) {
        float hv0 = hp[(size_t)hh * BB];
        float hv1 = hp[(size_t)(hh + 1) * BB];
        ull hv = pack2(hv0, hv1);
        const ull* wp = (const ull*)(ws + hh);
#pragma unroll
        for (int o = 0; o < NOUT; o++)
            FMA2(acc[o], hv, wp[o * 256]);
    }

    float* op = out + ((size_t)t * BB + b) * NOUT;
#pragma unroll
    for (int o = 0; o < NOUT; o++) {
        float2 v = unpack2(acc[o]);
        op[o] = v.x + v.y + bro[o];
    }
}

// =====================================================================
extern "C" void kernel_launch(void* const* d_in, const int* in_sizes, int n_in,
                              void* d_out, int out_size)
{
    const float* x   = (const float*)d_in[0];
    const float* Wxi = (const float*)d_in[1];
    const float* Wxf = (const float*)d_in[2];
    const float* Wxo = (const float*)d_in[3];
    const float* Wxc = (const float*)d_in[4];
    const float* Whi = (const float*)d_in[5];
    const float* bhi = (const float*)d_in[6];
    const float* Whf = (const float*)d_in[7];
    const float* bhf = (const float*)d_in[8];
    const float* Who = (const float*)d_in[9];
    const float* bho = (const float*)d_in[10];
    const float* Whc = (const float*)d_in[11];
    const float* bhc = (const float*)d_in[12];
    const float* Wro = (const float*)d_in[13];
    const float* bro = (const float*)d_in[14];
    float* out = (float*)d_out;

    // reset dataflow flags (stream-ordered, graph-capturable)
    void* flagptr = nullptr;
    cudaGetSymbolAddress(&flagptr, g_flags);
    cudaMemsetAsync(flagptr, 0, sizeof(unsigned) * TT * 2 * 64);

    const int smem_p1 = 85 * 258 * 4;               // 87,720 B
    const int smem_p2 = (32768 + 2 * 8192) * 4;     // 196,608 B
    const int smem_p3 = NOUT * HH * 4;              // 67,584 B

    cudaFuncSetAttribute(k_input_proj, cudaFuncAttributeMaxDynamicSharedMemorySize, smem_p1);
    cudaFuncSetAttribute(k_lstm_rec,   cudaFuncAttributeMaxDynamicSharedMemorySize, smem_p2);
    cudaFuncSetAttribute(k_readout,    cudaFuncAttributeMaxDynamicSharedMemorySize, smem_p3);

    k_input_proj<<<TT, 256, smem_p1>>>(x, Wxi, Wxf, Wxo, Wxc);
    k_lstm_rec<<<128, 128, smem_p2>>>(Whi, Whf, Who, Whc, bhi, bhf, bho, bhc);
    k_readout<<<TT, 256, smem_p3>>>(Wro, bro, out);
}